// round 8
// baseline (speedup 1.0000x reference)
#include <cuda_runtime.h>
#include <math.h>
#include <stdint.h>

typedef unsigned long long ull;

#define SEQ   1024
#define BATCH 64
#define DIN   256
#define HID   512
#define BUN   512

// ---------------- device scratch (no allocation allowed) ----------------
// g_C layout: [t][cl 16][r 4][j 512]   (cl = batch/4, r = row-in-cluster)
// holds C_t = x_t @ (Wbx@Wh) + (bb@Wh + bh)
__device__ __align__(16) float g_C[(size_t)SEQ * 16 * 4 * 512];   // 128 MB
__device__ __align__(16) float g_P[768 * 512];                    // P = Wb @ Wh
__device__ __align__(16) float g_c0[512];                         // bb@Wh + bh

// ---------------- packed f32x2 helpers ----------------
__device__ __forceinline__ ull ffma2(ull a, ull b, ull c) {
    ull d; asm("fma.rn.f32x2 %0, %1, %2, %3;" : "=l"(d) : "l"(a), "l"(b), "l"(c)); return d;
}
__device__ __forceinline__ ull add2(ull a, ull b) {
    ull d; asm("add.rn.f32x2 %0, %1, %2;" : "=l"(d) : "l"(a), "l"(b)); return d;
}
__device__ __forceinline__ ull pack2(float x, float y) {
    ull d; asm("mov.b64 %0, {%1, %2};" : "=l"(d) : "f"(x), "f"(y)); return d;
}
__device__ __forceinline__ float2 unpack2(ull a) {
    float2 r; asm("mov.b64 {%0, %1}, %2;" : "=f"(r.x), "=f"(r.y) : "l"(a)); return r;
}
__device__ __forceinline__ ull ldcg8(const float* p) {
    ull v; asm volatile("ld.global.cg.u64 %0, [%1];" : "=l"(v) : "l"(p)); return v;
}
__device__ __forceinline__ void stcg8(float* p, ull v) {
    asm volatile("st.global.cg.u64 [%0], %1;" :: "l"(p), "l"(v));
}
__device__ __forceinline__ uint32_t smem_u32(const void* p) {
    uint32_t a;
    asm("{ .reg .u64 t; cvta.to.shared.u64 t, %1; cvt.u32.u64 %0, t; }" : "=r"(a) : "l"(p));
    return a;
}
// store 8B into cluster-rank rk's smem at the same local offset
__device__ __forceinline__ void st_cluster_u64(uint32_t laddr, int rk, ull v) {
    uint32_t ra;
    asm volatile("mapa.shared::cluster.u32 %0, %1, %2;" : "=r"(ra) : "r"(laddr), "r"(rk));
    asm volatile("st.shared::cluster.u64 [%0], %1;" :: "r"(ra), "l"(v) : "memory");
}

// ---------------------------------------------------------------------------
// c0[u] = sum_j bb[j] * Wh[j][u] + bh[u]
// ---------------------------------------------------------------------------
__global__ void __launch_bounds__(512) c0_kernel(const float* __restrict__ bb,
                                                 const float* __restrict__ Wh,
                                                 const float* __restrict__ bh) {
    int u = threadIdx.x;
    float s = __ldg(&bh[u]);
#pragma unroll 8
    for (int j = 0; j < BUN; j++)
        s += __ldg(&bb[j]) * __ldg(&Wh[(size_t)j * HID + u]);
    g_c0[u] = s;
}

// ---------------------------------------------------------------------------
// P = Wb @ Wh   (768 x 512, K = 512). grid (8 colblk, 12 rowblk), 256 thr.
// ---------------------------------------------------------------------------
__global__ void __launch_bounds__(256) pmat_kernel(const float* __restrict__ Wb,
                                                   const float* __restrict__ Wh) {
    __shared__ float Asm[64 * 32];   // [r][k]
    __shared__ float Bsm[32 * 64];   // [k][j]
    const int tid = threadIdx.x;
    const int tx  = tid & 15;
    const int ty  = tid >> 4;
    const int jb  = blockIdx.x * 64;
    const int rb  = blockIdx.y * 64;

    float acc[16];
#pragma unroll
    for (int i = 0; i < 16; i++) acc[i] = 0.0f;

    for (int kt = 0; kt < 16; kt++) {
        const int kg = kt * 32;
#pragma unroll
        for (int i = 0; i < 2; i++) {
            int v = tid + 256 * i;
            int r = v >> 3, q = v & 7;
            *(float4*)&Asm[r * 32 + 4 * q] =
                __ldg((const float4*)&Wb[(size_t)(rb + r) * BUN + kg + 4 * q]);
        }
#pragma unroll
        for (int i = 0; i < 2; i++) {
            int v = tid + 256 * i;
            int kk = v >> 4, q = v & 15;
            *(float4*)&Bsm[kk * 64 + 4 * q] =
                __ldg((const float4*)&Wh[(size_t)(kg + kk) * HID + jb + 4 * q]);
        }
        __syncthreads();
#pragma unroll 8
        for (int kk = 0; kk < 32; kk++) {
            float4 b = *(const float4*)&Bsm[kk * 64 + 4 * tx];
            float a0 = Asm[(4 * ty + 0) * 32 + kk];
            float a1 = Asm[(4 * ty + 1) * 32 + kk];
            float a2 = Asm[(4 * ty + 2) * 32 + kk];
            float a3 = Asm[(4 * ty + 3) * 32 + kk];
            acc[0]  += a0 * b.x; acc[1]  += a0 * b.y; acc[2]  += a0 * b.z; acc[3]  += a0 * b.w;
            acc[4]  += a1 * b.x; acc[5]  += a1 * b.y; acc[6]  += a1 * b.z; acc[7]  += a1 * b.w;
            acc[8]  += a2 * b.x; acc[9]  += a2 * b.y; acc[10] += a2 * b.z; acc[11] += a2 * b.w;
            acc[12] += a3 * b.x; acc[13] += a3 * b.y; acc[14] += a3 * b.z; acc[15] += a3 * b.w;
        }
        __syncthreads();
    }
#pragma unroll
    for (int i = 0; i < 4; i++) {
        float4 o = make_float4(acc[4 * i], acc[4 * i + 1], acc[4 * i + 2], acc[4 * i + 3]);
        *(float4*)&g_P[(size_t)(rb + 4 * ty + i) * 512 + jb + 4 * tx] = o;
    }
}

// ---------------------------------------------------------------------------
// Precompute C[t][cl][r][j] = X[b][t][:256] @ N[.][j] + c0[j], b = 4*cl + r
// N = g_P rows 0..255. Tile 64 rows (all batch) x 256 cols, K-tile 32.
// grid (2 col-blocks, 1024 seq), 256 threads, per-thread 4r x 16c.
// ---------------------------------------------------------------------------
__global__ void __launch_bounds__(256) pre_kernel(const float* __restrict__ X) {
    __shared__ float AsmT[32 * 64];    // [k][b]  8 KB
    __shared__ float Bsm[32 * 256];    // [k][j]  32 KB

    const int tid = threadIdx.x;
    const int tx  = tid & 15;          // cols 16*tx .. +15
    const int ty  = tid >> 4;          // rows 4*ty .. +3
    const int s   = blockIdx.x >> 1 ? 0 : 0; // (unused guard)
    const int sy  = blockIdx.y;
    const int jb  = (blockIdx.x & 1) * 256;

    ull acc[32];                        // [r(4)][colpair(8)]
#pragma unroll
    for (int i = 0; i < 32; i++) acc[i] = 0ull;

    for (int kt = 0; kt < 8; kt++) {
        const int kg = kt * 32;
        // stage A transposed: AsmT[k][b] = X[b][sy][kg+k]; float4 loads along k
#pragma unroll
        for (int i = 0; i < 2; i++) {
            int v = tid + 256 * i;      // 0..511 float4 slots
            int b = v >> 3;             // 0..63
            int k4 = v & 7;             // k chunk
            float4 a = __ldg((const float4*)&X[(size_t)b * (SEQ * DIN) + (size_t)sy * DIN + kg + 4 * k4]);
            AsmT[(4 * k4 + 0) * 64 + b] = a.x;
            AsmT[(4 * k4 + 1) * 64 + b] = a.y;
            AsmT[(4 * k4 + 2) * 64 + b] = a.z;
            AsmT[(4 * k4 + 3) * 64 + b] = a.w;
        }
        // stage B: Bsm[k][j] from g_P rows kg..kg+31
#pragma unroll
        for (int i = 0; i < 8; i++) {
            int v = tid + 256 * i;      // 0..2047 float4 slots
            int k = v >> 6, q = v & 63;
            *(float4*)&Bsm[k * 256 + 4 * q] =
                *(const float4*)&g_P[(size_t)(kg + k) * 512 + jb + 4 * q];
        }
        __syncthreads();
#pragma unroll 8
        for (int k = 0; k < 32; k++) {
            const float* brow = &Bsm[k * 256 + 16 * tx];
            ulonglong2 w0 = *(const ulonglong2*)(brow);
            ulonglong2 w1 = *(const ulonglong2*)(brow + 4);
            ulonglong2 w2 = *(const ulonglong2*)(brow + 8);
            ulonglong2 w3 = *(const ulonglong2*)(brow + 12);
            float4 a4 = *(const float4*)&AsmT[k * 64 + 4 * ty];
            ull h0 = pack2(a4.x, a4.x), h1 = pack2(a4.y, a4.y);
            ull h2 = pack2(a4.z, a4.z), h3 = pack2(a4.w, a4.w);
            acc[0]  = ffma2(h0, w0.x, acc[0]);  acc[1]  = ffma2(h0, w0.y, acc[1]);
            acc[2]  = ffma2(h0, w1.x, acc[2]);  acc[3]  = ffma2(h0, w1.y, acc[3]);
            acc[4]  = ffma2(h0, w2.x, acc[4]);  acc[5]  = ffma2(h0, w2.y, acc[5]);
            acc[6]  = ffma2(h0, w3.x, acc[6]);  acc[7]  = ffma2(h0, w3.y, acc[7]);
            acc[8]  = ffma2(h1, w0.x, acc[8]);  acc[9]  = ffma2(h1, w0.y, acc[9]);
            acc[10] = ffma2(h1, w1.x, acc[10]); acc[11] = ffma2(h1, w1.y, acc[11]);
            acc[12] = ffma2(h1, w2.x, acc[12]); acc[13] = ffma2(h1, w2.y, acc[13]);
            acc[14] = ffma2(h1, w3.x, acc[14]); acc[15] = ffma2(h1, w3.y, acc[15]);
            acc[16] = ffma2(h2, w0.x, acc[16]); acc[17] = ffma2(h2, w0.y, acc[17]);
            acc[18] = ffma2(h2, w1.x, acc[18]); acc[19] = ffma2(h2, w1.y, acc[19]);
            acc[20] = ffma2(h2, w2.x, acc[20]); acc[21] = ffma2(h2, w2.y, acc[21]);
            acc[22] = ffma2(h2, w3.x, acc[22]); acc[23] = ffma2(h2, w3.y, acc[23]);
            acc[24] = ffma2(h3, w0.x, acc[24]); acc[25] = ffma2(h3, w0.y, acc[25]);
            acc[26] = ffma2(h3, w1.x, acc[26]); acc[27] = ffma2(h3, w1.y, acc[27]);
            acc[28] = ffma2(h3, w2.x, acc[28]); acc[29] = ffma2(h3, w2.y, acc[29]);
            acc[30] = ffma2(h3, w3.x, acc[30]); acc[31] = ffma2(h3, w3.y, acc[31]);
        }
        __syncthreads();
    }

    // epilogue: bias + store. b = 4*ty + r -> cl = ty, rloc = r.
    const ull* c0p = (const ull*)&g_c0[jb + 16 * tx];   // 8 ull pairs
#pragma unroll
    for (int r = 0; r < 4; r++) {
        float* dst = &g_C[(((size_t)sy * 16 + ty) * 4 + r) * 512 + jb + 16 * tx];
#pragma unroll
        for (int q = 0; q < 4; q++) {
            ull e0 = add2(acc[r * 8 + 2 * q],     c0p[2 * q]);
            ull e1 = add2(acc[r * 8 + 2 * q + 1], c0p[2 * q + 1]);
            float2 f0 = unpack2(e0), f1 = unpack2(e1);
            *(float4*)&dst[4 * q] = make_float4(f0.x, f0.y, f1.x, f1.y);
        }
    }
}

// ---------------------------------------------------------------------------
// Persistent recurrent kernel: 16 clusters x 8 CTAs. Cluster cl owns batch
// rows 4cl..4cl+3; CTA rank cb owns cols 64cb..64cb+63.
// Per step: cluster.sync -> kloop (h@M slice) -> smem reduce -> epilogue
// (tanh + ODE) -> DSMEM-broadcast h into all 8 CTAs' HT[next buf].
// ---------------------------------------------------------------------------
#define MS_F   32768                 // 512 x 64
#define HT_F   2048                  // [r 4][j 512] per buffer
#define RED_U  (32 * 130)            // [ks 32][o 128 ull + pad 2]
#define RECSM_BYTES ((MS_F + 2 * HT_F) * 4 + RED_U * 8)

__global__ void __launch_bounds__(256, 1) __cluster_dims__(8, 1, 1)
rec_kernel(const float* __restrict__ tau, float* __restrict__ out) {
    extern __shared__ float smem[];
    float* Ms  = smem;               // [k 512][64]
    float* HT0 = smem + MS_F;        // [r 4][j 512]
    float* HT1 = HT0 + HT_F;
    ull*   RED = (ull*)(HT1 + HT_F);

    const int tid = threadIdx.x;
    const int cb  = blockIdx.x & 7;      // rank in cluster (col block)
    const int cl  = blockIdx.x >> 3;     // cluster id (batch group)
    const int j0  = 64 * cb;
    const int cg  = tid & 7;             // 8 cols each
    const int ks  = tid >> 3;            // k-slice 0..31 (16 k each)

    // preload M slice (rows 256.. of g_P), held all 1024 steps
#pragma unroll
    for (int i = 0; i < 32; i++) {
        int v = tid + 256 * i;           // 0..8191 float4 slots
        int k = v >> 4, q = v & 15;
        *(float4*)&Ms[k * 64 + 4 * q] =
            *(const float4*)&g_P[(size_t)(256 + k) * 512 + j0 + 4 * q];
    }
    // zero initial h buffer
    for (int i = tid; i < HT_F; i += 256) HT0[i] = 0.0f;

    // epilogue thread state (tid < 128): output (row r, col pair j..j+1)
    ull ertau2 = 0ull, h_reg = 0ull;
    const float* cptr = g_C;
    float* optr = out;
    uint32_t ht0a = 0, ht1a = 0;
    if (tid < 128) {
        int r  = tid >> 5;
        int jp = tid & 31;
        int j  = j0 + 2 * jp;
        ertau2 = pack2(1.0f / __ldg(&tau[j]), 1.0f / __ldg(&tau[j + 1]));
        cptr = g_C + (((size_t)cl) * 4 + r) * 512 + j;           // + t*32768
        int b = 4 * cl + r;
        optr = out + ((size_t)b * SEQ) * HID + j;                // + t*512
        ht0a = smem_u32(HT0) + (uint32_t)(r * 512 + j) * 4u;
        ht1a = smem_u32(HT1) + (uint32_t)(r * 512 + j) * 4u;
    }

    const float* wbase = Ms + (16 * ks) * 64 + 8 * cg;
    ull* rwbase = RED + ks * 130 + 4 * cg;

    for (int t = 0; t < SEQ; t++) {
        // cluster-wide barrier: previous step's h broadcasts complete,
        // and peers are done reading the buffer we are about to overwrite.
        asm volatile("barrier.cluster.arrive.aligned;" ::: "memory");
        asm volatile("barrier.cluster.wait.aligned;"   ::: "memory");

        const float* cur = (t & 1) ? HT1 : HT0;

        // issue C load early (DRAM latency hidden under kloop)
        ull cv = 0ull;
        if (tid < 128) cv = ldcg8(cptr);

        // ---- kloop: 16 k per thread, 8 cols x 4 rows ----
        ull acc[16];
#pragma unroll
        for (int i = 0; i < 16; i++) acc[i] = 0ull;
        {
            const float* wrow = wbase;
            const float* hK = cur + 16 * ks;
#pragma unroll
            for (int i = 0; i < 16; i++) {
                ulonglong2 wA = *(const ulonglong2*)(wrow);
                ulonglong2 wB = *(const ulonglong2*)(wrow + 4);
                float ha = hK[0], hb = hK[512], hc = hK[1024], hd = hK[1536];
                ull h0 = pack2(ha, ha), h1 = pack2(hb, hb);
                ull h2 = pack2(hc, hc), h3 = pack2(hd, hd);
                acc[0]  = ffma2(h0, wA.x, acc[0]);
                acc[1]  = ffma2(h0, wA.y, acc[1]);
                acc[2]  = ffma2(h0, wB.x, acc[2]);
                acc[3]  = ffma2(h0, wB.y, acc[3]);
                acc[4]  = ffma2(h1, wA.x, acc[4]);
                acc[5]  = ffma2(h1, wA.y, acc[5]);
                acc[6]  = ffma2(h1, wB.x, acc[6]);
                acc[7]  = ffma2(h1, wB.y, acc[7]);
                acc[8]  = ffma2(h2, wA.x, acc[8]);
                acc[9]  = ffma2(h2, wA.y, acc[9]);
                acc[10] = ffma2(h2, wB.x, acc[10]);
                acc[11] = ffma2(h2, wB.y, acc[11]);
                acc[12] = ffma2(h3, wA.x, acc[12]);
                acc[13] = ffma2(h3, wA.y, acc[13]);
                acc[14] = ffma2(h3, wB.x, acc[14]);
                acc[15] = ffma2(h3, wB.y, acc[15]);
                wrow += 64; hK += 1;
            }
        }
        // ---- write partials: RED[ks][o], o = 32r + 4cg + cp ----
#pragma unroll
        for (int r = 0; r < 4; r++) {
            ulonglong2 v0, v1;
            v0.x = acc[4 * r + 0]; v0.y = acc[4 * r + 1];
            v1.x = acc[4 * r + 2]; v1.y = acc[4 * r + 3];
            *(ulonglong2*)(rwbase + 32 * r)     = v0;
            *(ulonglong2*)(rwbase + 32 * r + 2) = v1;
        }
        __syncthreads();

        // ---- reduce + epilogue (128 threads; o = tid) ----
        if (tid < 128) {
            const ull* rb = RED + tid;
            ull s0 = rb[0];
            ull s1 = rb[130];
            ull s2 = rb[2 * 130];
            ull s3 = rb[3 * 130];
#pragma unroll
            for (int i = 4; i < 32; i += 4) {
                s0 = add2(s0, rb[(i + 0) * 130]);
                s1 = add2(s1, rb[(i + 1) * 130]);
                s2 = add2(s2, rb[(i + 2) * 130]);
                s3 = add2(s3, rb[(i + 3) * 130]);
            }
            float2 z = unpack2(add2(add2(s0, s1), add2(s2, s3)));
            float2 c = unpack2(cv);
            float d0 = tanhf(z.x + c.x);
            float d1 = tanhf(z.y + c.y);
            float2 h  = unpack2(h_reg);
            float2 rt = unpack2(ertau2);
            float hn0 = h.x + (d0 - h.x) * rt.x;
            float hn1 = h.y + (d1 - h.y) * rt.y;
            h_reg = pack2(hn0, hn1);
            // broadcast h into every CTA's next-step buffer (incl. self)
            uint32_t wa = (t & 1) ? ht0a : ht1a;
#pragma unroll
            for (int rk = 0; rk < 8; rk++) st_cluster_u64(wa, rk, h_reg);
            // outputs (nobody reads these; off the sync path)
            stcg8(optr, h_reg);
            cptr += 16 * 4 * 512;
            optr += 512;
        }
        // NOTE: RED reuse next step is safe: all threads pass the cluster
        // barrier (superset of __syncthreads) before new partials are written.
    }
    // no CTA may exit while peers' DSMEM stores to it may be in flight
    asm volatile("barrier.cluster.arrive.aligned;" ::: "memory");
    asm volatile("barrier.cluster.wait.aligned;"   ::: "memory");
}

// ---------------------------------------------------------------------------
extern "C" void kernel_launch(void* const* d_in, const int* in_sizes, int n_in,
                              void* d_out, int out_size) {
    (void)in_sizes; (void)n_in; (void)out_size;
    const float* X   = (const float*)d_in[0];
    const float* Wb  = (const float*)d_in[1];
    const float* bb  = (const float*)d_in[2];
    const float* Wh  = (const float*)d_in[3];
    const float* bh  = (const float*)d_in[4];
    const float* tau = (const float*)d_in[5];
    float* out = (float*)d_out;

    cudaFuncSetAttribute(rec_kernel, cudaFuncAttributeMaxDynamicSharedMemorySize, RECSM_BYTES);

    c0_kernel<<<1, 512>>>(bb, Wh, bh);
    dim3 pgrid(8, 12);
    pmat_kernel<<<pgrid, 256>>>(Wb, Wh);
    dim3 cgrid(2, SEQ);
    pre_kernel<<<cgrid, 256>>>(X);
    rec_kernel<<<128, 256, RECSM_BYTES>>>(tau, out);
}

// round 9
// speedup vs baseline: 1.4473x; 1.4473x over previous
#include <cuda_runtime.h>
#include <math.h>
#include <stdint.h>

typedef unsigned long long ull;

#define SEQ   1024
#define BATCH 64
#define DIN   256
#define HID   512
#define BUN   512

// ---------------- device scratch (no allocation allowed) ----------------
// g_C layout: [t][g 16][r 4][j 512]  (g = batch/4, r = row-in-group)
// holds C_t = x_t @ (Wbx@Wh) + (bb@Wh + bh)
__device__ __align__(16) float g_C[(size_t)SEQ * 16 * 4 * 512];   // 128 MB
__device__ __align__(16) float g_H[16 * 512 * 4];                 // [g][j][r]
__device__ __align__(16) float g_P[768 * 512];                    // P = Wb @ Wh
__device__ __align__(16) float g_c0[512];                         // bb@Wh + bh
__device__ unsigned g_ctr[512];                                   // 1 counter / group, 128B apart

// ---------------- packed f32x2 helpers ----------------
__device__ __forceinline__ ull ffma2(ull a, ull b, ull c) {
    ull d; asm("fma.rn.f32x2 %0, %1, %2, %3;" : "=l"(d) : "l"(a), "l"(b), "l"(c)); return d;
}
__device__ __forceinline__ ull add2(ull a, ull b) {
    ull d; asm("add.rn.f32x2 %0, %1, %2;" : "=l"(d) : "l"(a), "l"(b)); return d;
}
__device__ __forceinline__ ull pack2(float x, float y) {
    ull d; asm("mov.b64 %0, {%1, %2};" : "=l"(d) : "f"(x), "f"(y)); return d;
}
__device__ __forceinline__ float2 unpack2(ull a) {
    float2 r; asm("mov.b64 {%0, %1}, %2;" : "=f"(r.x), "=f"(r.y) : "l"(a)); return r;
}

// ---------------- L1-bypassing global access ----------------
__device__ __forceinline__ ull ldcg8(const float* p) {
    ull v; asm volatile("ld.global.cg.u64 %0, [%1];" : "=l"(v) : "l"(p)); return v;
}
__device__ __forceinline__ void stcg8(float* p, ull v) {
    asm volatile("st.global.cg.u64 [%0], %1;" :: "l"(p), "l"(v));
}
__device__ __forceinline__ float ldcgf(const float* p) {
    float v; asm volatile("ld.global.cg.f32 %0, [%1];" : "=f"(v) : "l"(p)); return v;
}
__device__ __forceinline__ void stcgf(float* p, float v) {
    asm volatile("st.global.cg.f32 [%0], %1;" :: "l"(p), "f"(v));
}

// ---------------- init: zero H and barrier counters (every replay) ------
__global__ void __launch_bounds__(256) init_kernel() {
    int t = threadIdx.x;
    g_ctr[t] = 0u;
    g_ctr[t + 256] = 0u;
    for (int i = t; i < 16 * 512 * 4; i += 256) g_H[i] = 0.0f;
}

// ---------------------------------------------------------------------------
// c0[u] = sum_j bb[j] * Wh[j][u] + bh[u]
// ---------------------------------------------------------------------------
__global__ void __launch_bounds__(512) c0_kernel(const float* __restrict__ bb,
                                                 const float* __restrict__ Wh,
                                                 const float* __restrict__ bh) {
    int u = threadIdx.x;
    float s = __ldg(&bh[u]);
#pragma unroll 8
    for (int j = 0; j < BUN; j++)
        s += __ldg(&bb[j]) * __ldg(&Wh[(size_t)j * HID + u]);
    g_c0[u] = s;
}

// ---------------------------------------------------------------------------
// P = Wb @ Wh   (768 x 512, K = 512). grid (8 colblk, 12 rowblk), 256 thr.
// ---------------------------------------------------------------------------
__global__ void __launch_bounds__(256) pmat_kernel(const float* __restrict__ Wb,
                                                   const float* __restrict__ Wh) {
    __shared__ float Asm[64 * 32];   // [r][k]
    __shared__ float Bsm[32 * 64];   // [k][j]
    const int tid = threadIdx.x;
    const int tx  = tid & 15;
    const int ty  = tid >> 4;
    const int jb  = blockIdx.x * 64;
    const int rb  = blockIdx.y * 64;

    float acc[16];
#pragma unroll
    for (int i = 0; i < 16; i++) acc[i] = 0.0f;

    for (int kt = 0; kt < 16; kt++) {
        const int kg = kt * 32;
#pragma unroll
        for (int i = 0; i < 2; i++) {
            int v = tid + 256 * i;
            int r = v >> 3, q = v & 7;
            *(float4*)&Asm[r * 32 + 4 * q] =
                __ldg((const float4*)&Wb[(size_t)(rb + r) * BUN + kg + 4 * q]);
        }
#pragma unroll
        for (int i = 0; i < 2; i++) {
            int v = tid + 256 * i;
            int kk = v >> 4, q = v & 15;
            *(float4*)&Bsm[kk * 64 + 4 * q] =
                __ldg((const float4*)&Wh[(size_t)(kg + kk) * HID + jb + 4 * q]);
        }
        __syncthreads();
#pragma unroll 8
        for (int kk = 0; kk < 32; kk++) {
            float4 b = *(const float4*)&Bsm[kk * 64 + 4 * tx];
            float a0 = Asm[(4 * ty + 0) * 32 + kk];
            float a1 = Asm[(4 * ty + 1) * 32 + kk];
            float a2 = Asm[(4 * ty + 2) * 32 + kk];
            float a3 = Asm[(4 * ty + 3) * 32 + kk];
            acc[0]  += a0 * b.x; acc[1]  += a0 * b.y; acc[2]  += a0 * b.z; acc[3]  += a0 * b.w;
            acc[4]  += a1 * b.x; acc[5]  += a1 * b.y; acc[6]  += a1 * b.z; acc[7]  += a1 * b.w;
            acc[8]  += a2 * b.x; acc[9]  += a2 * b.y; acc[10] += a2 * b.z; acc[11] += a2 * b.w;
            acc[12] += a3 * b.x; acc[13] += a3 * b.y; acc[14] += a3 * b.z; acc[15] += a3 * b.w;
        }
        __syncthreads();
    }
#pragma unroll
    for (int i = 0; i < 4; i++) {
        float4 o = make_float4(acc[4 * i], acc[4 * i + 1], acc[4 * i + 2], acc[4 * i + 3]);
        *(float4*)&g_P[(size_t)(rb + 4 * ty + i) * 512 + jb + 4 * tx] = o;
    }
}

// ---------------------------------------------------------------------------
// Precompute C[t][g][r][j] = X[b][t][:256] @ N[.][j] + c0[j], b = 4g + r
// N = g_P rows 0..255. grid (8 col-blocks of 64, 1024 seq), 256 threads.
// (R6-proven body; only the epilogue layout changed.)
// ---------------------------------------------------------------------------
__global__ void __launch_bounds__(256) pre_kernel(const float* __restrict__ X) {
    __shared__ float AsmT[64 * 64];   // [k][b]
    __shared__ float Bsm[64 * 64];    // [k][j]

    const int tid = threadIdx.x;
    const int tx  = tid & 15;
    const int ty  = tid >> 4;
    const int s   = blockIdx.y;
    const int jb  = blockIdx.x * 64;

    ull acc[8];
#pragma unroll
    for (int i = 0; i < 8; i++) acc[i] = 0ull;

    for (int kt = 0; kt < 4; kt++) {
        const int kg = kt * 64;
#pragma unroll
        for (int i = 0; i < 4; i++) {
            int v = tid + 256 * i;     // 0..1023
            int k = v & 63;
            int bg = v >> 6;           // 0..15 (4 batch rows each)
            float4 a;
            a.x = __ldg(&X[(size_t)(4 * bg + 0) * SEQ * DIN + (size_t)s * DIN + kg + k]);
            a.y = __ldg(&X[(size_t)(4 * bg + 1) * SEQ * DIN + (size_t)s * DIN + kg + k]);
            a.z = __ldg(&X[(size_t)(4 * bg + 2) * SEQ * DIN + (size_t)s * DIN + kg + k]);
            a.w = __ldg(&X[(size_t)(4 * bg + 3) * SEQ * DIN + (size_t)s * DIN + kg + k]);
            *(float4*)&AsmT[k * 64 + 4 * bg] = a;
        }
#pragma unroll
        for (int i = 0; i < 4; i++) {
            int v = tid + 256 * i;
            int k = v >> 4;
            int q = v & 15;
            *(float4*)&Bsm[k * 64 + 4 * q] =
                *(const float4*)&g_P[(size_t)(kg + k) * 512 + jb + 4 * q];
        }
        __syncthreads();
#pragma unroll 8
        for (int k = 0; k < 64; k++) {
            float4 w = *(const float4*)&Bsm[k * 64 + 4 * tx];
            ulonglong2 a = *(const ulonglong2*)&AsmT[k * 64 + 4 * ty];
            ull w0 = pack2(w.x, w.x), w1 = pack2(w.y, w.y);
            ull w2 = pack2(w.z, w.z), w3 = pack2(w.w, w.w);
            acc[0] = ffma2(a.x, w0, acc[0]);
            acc[1] = ffma2(a.x, w1, acc[1]);
            acc[2] = ffma2(a.x, w2, acc[2]);
            acc[3] = ffma2(a.x, w3, acc[3]);
            acc[4] = ffma2(a.y, w0, acc[4]);
            acc[5] = ffma2(a.y, w1, acc[5]);
            acc[6] = ffma2(a.y, w2, acc[6]);
            acc[7] = ffma2(a.y, w3, acc[7]);
        }
        __syncthreads();
    }

    // epilogue: rows b = 4ty + r -> group g = ty, local row r. Store along j.
    const int g = ty;
    float4 bias = *(const float4*)&g_c0[jb + 4 * tx];
    float2 u[8];
#pragma unroll
    for (int i = 0; i < 8; i++) u[i] = unpack2(acc[i]);
#pragma unroll
    for (int r = 0; r < 4; r++) {
        int half = (r >> 1) * 4;
        int sel  = r & 1;
        float4 v;
        v.x = (sel ? u[half + 0].y : u[half + 0].x) + bias.x;
        v.y = (sel ? u[half + 1].y : u[half + 1].x) + bias.y;
        v.z = (sel ? u[half + 2].y : u[half + 2].x) + bias.z;
        v.w = (sel ? u[half + 3].y : u[half + 3].x) + bias.w;
        *(float4*)&g_C[(((size_t)s * 16 + g) * 4 + r) * 512 + jb + 4 * tx] = v;
    }
}

// ---------------------------------------------------------------------------
// Persistent recurrent kernel: 128 CTAs = 16 groups x 8 CTAs.
// Group g owns batch rows 4g..4g+3; CTA cb owns cols 64cb..64cb+63.
// Weights live in REGISTERS (64 packed ulls / thread) for all 1024 steps.
// Per step: stage h (packed splats) -> reg-weight kloop -> shfl k-reduce ->
// smem cross-warp reduce -> tanh/ODE epilogue -> L2 h exchange + group barrier.
// ---------------------------------------------------------------------------
__global__ void __launch_bounds__(256, 1) rec_kernel(const float* __restrict__ tau,
                                                     float* __restrict__ out) {
    __shared__ ull HTp[2048];        // h packed splats: [j 512][r 4]
    __shared__ ull RED[8 * 8 * 18];  // [warp 8][lane 8][16 + 2 pad]

    const int tid  = threadIdx.x;
    const int lane = tid & 31;
    const int warp = tid >> 5;
    const int cb   = blockIdx.x & 7;     // col block in group
    const int g    = blockIdx.x >> 3;    // batch group 0..15
    const int j0   = 64 * cb;
    const int cg   = tid & 7;            // 8 cols each
    const int ks   = tid >> 3;           // k-slice 0..31 (16 k each)

    // ---- weights into registers: M[k][j] = g_P[256+k][j] ----
    ull wreg[64];                        // [i 16][colpair 4]
    {
        const float* ws = &g_P[(size_t)(256 + 16 * ks) * 512 + j0 + 8 * cg];
#pragma unroll
        for (int i = 0; i < 16; i++) {
            float4 a = __ldg((const float4*)(ws + (size_t)i * 512));
            float4 b = __ldg((const float4*)(ws + (size_t)i * 512 + 4));
            wreg[4 * i + 0] = pack2(a.x, a.y);
            wreg[4 * i + 1] = pack2(a.z, a.w);
            wreg[4 * i + 2] = pack2(b.x, b.y);
            wreg[4 * i + 3] = pack2(b.z, b.w);
        }
    }

    // ---- epilogue state (tid < 128): output o = colpair*4 + r ----
    ull ertau2 = 0ull, h_reg = 0ull, cv = 0ull;
    const float* cptr = g_C;
    float *optr = out, *hdst = g_H;
    if (tid < 128) {
        int cpair = tid >> 2;            // 0..31
        int r     = tid & 3;
        int j     = j0 + 2 * cpair;
        ertau2 = pack2(1.0f / __ldg(&tau[j]), 1.0f / __ldg(&tau[j + 1]));
        cptr = g_C + (((size_t)g) * 4 + r) * 512 + j;    // + t*32768
        optr = out + ((size_t)(4 * g + r) * SEQ) * 512 + j;  // + t*512
        hdst = g_H + g * 2048 + j * 4 + r;
        cv = ldcg8(cptr);                // C for t=0
    }

    const float* hsrc = g_H + g * 2048;  // flat [j][r], 2048 floats
    unsigned* ctr = &g_ctr[g * 32];
    unsigned bt = 0;

    for (int t = 0; t < SEQ; t++) {
        // ---- stage h: load 8 scalars (coalesced), pack splats into smem ----
#pragma unroll
        for (int i = 0; i < 8; i++) {
            float v = ldcgf(hsrc + tid + 256 * i);
            HTp[tid + 256 * i] = pack2(v, v);
        }
        __syncthreads();

        // ---- kloop: 16 k, weights from registers, h broadcast from smem ----
        ull acc[16];                     // [colpair 4][row 4]
#pragma unroll
        for (int i = 0; i < 16; i++) acc[i] = 0ull;
        {
            const ull* hp = &HTp[64 * ks];
#pragma unroll
            for (int i = 0; i < 16; i++) {
                ulonglong2 hA = *(const ulonglong2*)(hp + 4 * i);      // rows 0,1
                ulonglong2 hB = *(const ulonglong2*)(hp + 4 * i + 2);  // rows 2,3
                ull w0 = wreg[4 * i + 0], w1 = wreg[4 * i + 1];
                ull w2 = wreg[4 * i + 2], w3 = wreg[4 * i + 3];
                acc[0]  = ffma2(w0, hA.x, acc[0]);
                acc[1]  = ffma2(w0, hA.y, acc[1]);
                acc[2]  = ffma2(w0, hB.x, acc[2]);
                acc[3]  = ffma2(w0, hB.y, acc[3]);
                acc[4]  = ffma2(w1, hA.x, acc[4]);
                acc[5]  = ffma2(w1, hA.y, acc[5]);
                acc[6]  = ffma2(w1, hB.x, acc[6]);
                acc[7]  = ffma2(w1, hB.y, acc[7]);
                acc[8]  = ffma2(w2, hA.x, acc[8]);
                acc[9]  = ffma2(w2, hA.y, acc[9]);
                acc[10] = ffma2(w2, hB.x, acc[10]);
                acc[11] = ffma2(w2, hB.y, acc[11]);
                acc[12] = ffma2(w3, hA.x, acc[12]);
                acc[13] = ffma2(w3, hA.y, acc[13]);
                acc[14] = ffma2(w3, hB.x, acc[14]);
                acc[15] = ffma2(w3, hB.y, acc[15]);
            }
        }

        // ---- intra-warp k-reduce: fold the 4 k-slices in this warp ----
#pragma unroll
        for (int i = 0; i < 16; i++)
            acc[i] = add2(acc[i], __shfl_xor_sync(0xffffffffu, acc[i], 8));
#pragma unroll
        for (int i = 0; i < 16; i++)
            acc[i] = add2(acc[i], __shfl_xor_sync(0xffffffffu, acc[i], 16));

        // lanes 0..7 (one per cg) hold the warp's partial for 16 outputs
        if (lane < 8) {
            ull* rw = &RED[(warp * 8 + lane) * 18];
#pragma unroll
            for (int m = 0; m < 8; m++) {
                ulonglong2 v; v.x = acc[2 * m]; v.y = acc[2 * m + 1];
                *(ulonglong2*)(rw + 2 * m) = v;
            }
        }
        __syncthreads();

        bt += 8;
        // ---- cross-warp reduce + epilogue ----
        if (tid < 128) {
            const ull* rb = &RED[(tid >> 4) * 18 + (tid & 15)];
            ull s0 = rb[0], s1 = rb[144], s2 = rb[288], s3 = rb[432];
            s0 = add2(s0, rb[576]);
            s1 = add2(s1, rb[720]);
            s2 = add2(s2, rb[864]);
            s3 = add2(s3, rb[1008]);
            float2 z = unpack2(add2(add2(s0, s1), add2(s2, s3)));
            float2 c = unpack2(cv);
            float d0 = tanhf(z.x + c.x);
            float d1 = tanhf(z.y + c.y);
            float2 h  = unpack2(h_reg);
            float2 rt = unpack2(ertau2);
            float hn0 = h.x + (d0 - h.x) * rt.x;
            float hn1 = h.y + (d1 - h.y) * rt.y;
            h_reg = pack2(hn0, hn1);
            stcgf(hdst, hn0);            // h[j][r]
            stcgf(hdst + 4, hn1);        // h[j+1][r]
            stcg8(optr, h_reg);          // out[b][t][j..j+1]
            optr += 512;
            __threadfence();
        }
        __syncthreads();

        // prefetch next step's C under the barrier wait (input-only, no hazard)
        if (tid < 128 && t + 1 < SEQ) {
            cptr += 16 * 4 * 512;
            cv = ldcg8(cptr);
        }
        if (tid == 0) {
            asm volatile("red.release.gpu.global.add.u32 [%0], %1;" :: "l"(ctr), "r"(1u) : "memory");
            unsigned v;
            do {
                asm volatile("ld.acquire.gpu.global.u32 %0, [%1];" : "=r"(v) : "l"(ctr) : "memory");
            } while (v < bt);
        }
        __syncthreads();
    }
}

// ---------------------------------------------------------------------------
extern "C" void kernel_launch(void* const* d_in, const int* in_sizes, int n_in,
                              void* d_out, int out_size) {
    (void)in_sizes; (void)n_in; (void)out_size;
    const float* X   = (const float*)d_in[0];
    const float* Wb  = (const float*)d_in[1];
    const float* bb  = (const float*)d_in[2];
    const float* Wh  = (const float*)d_in[3];
    const float* bh  = (const float*)d_in[4];
    const float* tau = (const float*)d_in[5];
    float* out = (float*)d_out;

    init_kernel<<<1, 256>>>();
    c0_kernel<<<1, 512>>>(bb, Wh, bh);
    dim3 pgrid(8, 12);
    pmat_kernel<<<pgrid, 256>>>(Wb, Wh);
    dim3 cgrid(8, SEQ);
    pre_kernel<<<cgrid, 256>>>(X);
    rec_kernel<<<128, 256>>>(tau, out);
}

// round 10
// speedup vs baseline: 1.7487x; 1.2082x over previous
#include <cuda_runtime.h>
#include <math.h>
#include <stdint.h>

typedef unsigned long long ull;

#define SEQ   1024
#define BATCH 64
#define DIN   256
#define HID   512
#define BUN   512

// ---------------- device scratch (no allocation allowed) ----------------
// g_C layout: [t][g 8][j 512][r 8]  (g = batch/8, r = row-in-group)
// holds C_t = x_t @ (Wbx@Wh) + (bb@Wh + bh)
__device__ __align__(16) float g_C[(size_t)SEQ * 8 * 512 * 8];    // 128 MB
__device__ __align__(16) float g_H[8 * 512 * 8];                  // [g][j][r]
__device__ __align__(16) float g_P[768 * 512];                    // P = Wb @ Wh
__device__ __align__(16) float g_c0[512];                         // bb@Wh + bh
__device__ unsigned g_ctr[256];                                   // 1 counter / group, 128B apart

// ---------------- packed f32x2 helpers ----------------
__device__ __forceinline__ ull ffma2(ull a, ull b, ull c) {
    ull d; asm("fma.rn.f32x2 %0, %1, %2, %3;" : "=l"(d) : "l"(a), "l"(b), "l"(c)); return d;
}
__device__ __forceinline__ ull add2(ull a, ull b) {
    ull d; asm("add.rn.f32x2 %0, %1, %2;" : "=l"(d) : "l"(a), "l"(b)); return d;
}
__device__ __forceinline__ ull pack2(float x, float y) {
    ull d; asm("mov.b64 %0, {%1, %2};" : "=l"(d) : "f"(x), "f"(y)); return d;
}
__device__ __forceinline__ float2 unpack2(ull a) {
    float2 r; asm("mov.b64 {%0, %1}, %2;" : "=f"(r.x), "=f"(r.y) : "l"(a)); return r;
}

// ---------------- L1-bypassing global access ----------------
__device__ __forceinline__ float4 ldcg4(const float* p) {
    float4 v;
    asm volatile("ld.global.cg.v4.f32 {%0,%1,%2,%3}, [%4];"
                 : "=f"(v.x), "=f"(v.y), "=f"(v.z), "=f"(v.w) : "l"(p));
    return v;
}
__device__ __forceinline__ ull ldcg8(const float* p) {
    ull v; asm volatile("ld.global.cg.u64 %0, [%1];" : "=l"(v) : "l"(p)); return v;
}
__device__ __forceinline__ void stcg8(float* p, ull v) {
    asm volatile("st.global.cg.u64 [%0], %1;" :: "l"(p), "l"(v));
}

// ---------------- init: zero H and barrier counters (every replay) ------
__global__ void __launch_bounds__(256) init_kernel() {
    int t = threadIdx.x;
    g_ctr[t] = 0u;
    for (int i = t; i < 8 * 512 * 8; i += 256) g_H[i] = 0.0f;
}

// ---------------------------------------------------------------------------
// c0[u] = sum_j bb[j] * Wh[j][u] + bh[u]
// ---------------------------------------------------------------------------
__global__ void __launch_bounds__(512) c0_kernel(const float* __restrict__ bb,
                                                 const float* __restrict__ Wh,
                                                 const float* __restrict__ bh) {
    int u = threadIdx.x;
    float s = __ldg(&bh[u]);
#pragma unroll 8
    for (int j = 0; j < BUN; j++)
        s += __ldg(&bb[j]) * __ldg(&Wh[(size_t)j * HID + u]);
    g_c0[u] = s;
}

// ---------------------------------------------------------------------------
// P = Wb @ Wh   (768 x 512, K = 512). grid (8 colblk, 12 rowblk), 256 thr.
// ---------------------------------------------------------------------------
__global__ void __launch_bounds__(256) pmat_kernel(const float* __restrict__ Wb,
                                                   const float* __restrict__ Wh) {
    __shared__ float Asm[64 * 32];   // [r][k]
    __shared__ float Bsm[32 * 64];   // [k][j]
    const int tid = threadIdx.x;
    const int tx  = tid & 15;
    const int ty  = tid >> 4;
    const int jb  = blockIdx.x * 64;
    const int rb  = blockIdx.y * 64;

    float acc[16];
#pragma unroll
    for (int i = 0; i < 16; i++) acc[i] = 0.0f;

    for (int kt = 0; kt < 16; kt++) {
        const int kg = kt * 32;
#pragma unroll
        for (int i = 0; i < 2; i++) {
            int v = tid + 256 * i;
            int r = v >> 3, q = v & 7;
            *(float4*)&Asm[r * 32 + 4 * q] =
                __ldg((const float4*)&Wb[(size_t)(rb + r) * BUN + kg + 4 * q]);
        }
#pragma unroll
        for (int i = 0; i < 2; i++) {
            int v = tid + 256 * i;
            int kk = v >> 4, q = v & 15;
            *(float4*)&Bsm[kk * 64 + 4 * q] =
                __ldg((const float4*)&Wh[(size_t)(kg + kk) * HID + jb + 4 * q]);
        }
        __syncthreads();
#pragma unroll 8
        for (int kk = 0; kk < 32; kk++) {
            float4 b = *(const float4*)&Bsm[kk * 64 + 4 * tx];
            float a0 = Asm[(4 * ty + 0) * 32 + kk];
            float a1 = Asm[(4 * ty + 1) * 32 + kk];
            float a2 = Asm[(4 * ty + 2) * 32 + kk];
            float a3 = Asm[(4 * ty + 3) * 32 + kk];
            acc[0]  += a0 * b.x; acc[1]  += a0 * b.y; acc[2]  += a0 * b.z; acc[3]  += a0 * b.w;
            acc[4]  += a1 * b.x; acc[5]  += a1 * b.y; acc[6]  += a1 * b.z; acc[7]  += a1 * b.w;
            acc[8]  += a2 * b.x; acc[9]  += a2 * b.y; acc[10] += a2 * b.z; acc[11] += a2 * b.w;
            acc[12] += a3 * b.x; acc[13] += a3 * b.y; acc[14] += a3 * b.z; acc[15] += a3 * b.w;
        }
        __syncthreads();
    }
#pragma unroll
    for (int i = 0; i < 4; i++) {
        float4 o = make_float4(acc[4 * i], acc[4 * i + 1], acc[4 * i + 2], acc[4 * i + 3]);
        *(float4*)&g_P[(size_t)(rb + 4 * ty + i) * 512 + jb + 4 * tx] = o;
    }
}

// ---------------------------------------------------------------------------
// Precompute C[t][g][j][r] = X[b][t][:256] @ N[.][j] + c0[j], b = 8g + r
// v2: tile 64 rows x 256 cols, K-tile 32, per-thread 8r x 8c (1 B/MAC).
// Cols per thread: {4tx..4tx+3} and {128+4tx..+3} (conflict-free LDS.128).
// grid (2 col-blocks, 1024 seq), 256 threads.
// ---------------------------------------------------------------------------
__global__ void __launch_bounds__(256) pre_kernel(const float* __restrict__ X) {
    __shared__ float AsmT[32 * 64];    // [k][b]  8 KB
    __shared__ float Bsm[32 * 256];    // [k][j]  32 KB

    const int tid = threadIdx.x;
    const int tx  = tid & 31;          // lane: col groups 4tx and 128+4tx
    const int ty  = tid >> 5;          // warp: rows 8ty..8ty+7 (one batch group)
    const int s   = blockIdx.y;
    const int jb  = blockIdx.x * 256;

    ull acc[32];                        // [rowpair 4][col 8]
#pragma unroll
    for (int i = 0; i < 32; i++) acc[i] = 0ull;

    for (int kt = 0; kt < 8; kt++) {
        const int kg = kt * 32;
        // stage A transposed: AsmT[k][b] = X[b][s][kg+k]
#pragma unroll
        for (int i = 0; i < 2; i++) {
            int v = tid + 256 * i;      // 0..511 float4-slots
            int b = v >> 3, q = v & 7;
            float4 a = __ldg((const float4*)&X[(size_t)b * (SEQ * DIN) + (size_t)s * DIN + kg + 4 * q]);
            AsmT[(4 * q + 0) * 64 + b] = a.x;
            AsmT[(4 * q + 1) * 64 + b] = a.y;
            AsmT[(4 * q + 2) * 64 + b] = a.z;
            AsmT[(4 * q + 3) * 64 + b] = a.w;
        }
        // stage B: Bsm[k][j] from g_P rows kg..kg+31 (L2-resident)
#pragma unroll
        for (int i = 0; i < 8; i++) {
            int v = tid + 256 * i;      // 0..2047 float4-slots
            int k = v >> 6, q = v & 63;
            *(float4*)&Bsm[k * 256 + 4 * q] =
                *(const float4*)&g_P[(size_t)(kg + k) * 512 + jb + 4 * q];
        }
        __syncthreads();
#pragma unroll 8
        for (int k = 0; k < 32; k++) {
            float4 wA = *(const float4*)&Bsm[k * 256 + 4 * tx];
            float4 wB = *(const float4*)&Bsm[k * 256 + 128 + 4 * tx];
            ulonglong2 aA = *(const ulonglong2*)&AsmT[k * 64 + 8 * ty];      // rows 0-3
            ulonglong2 aB = *(const ulonglong2*)&AsmT[k * 64 + 8 * ty + 4];  // rows 4-7
            ull w0 = pack2(wA.x, wA.x), w1 = pack2(wA.y, wA.y);
            ull w2 = pack2(wA.z, wA.z), w3 = pack2(wA.w, wA.w);
            ull w4 = pack2(wB.x, wB.x), w5 = pack2(wB.y, wB.y);
            ull w6 = pack2(wB.z, wB.z), w7 = pack2(wB.w, wB.w);
            acc[0]  = ffma2(aA.x, w0, acc[0]);
            acc[1]  = ffma2(aA.x, w1, acc[1]);
            acc[2]  = ffma2(aA.x, w2, acc[2]);
            acc[3]  = ffma2(aA.x, w3, acc[3]);
            acc[4]  = ffma2(aA.x, w4, acc[4]);
            acc[5]  = ffma2(aA.x, w5, acc[5]);
            acc[6]  = ffma2(aA.x, w6, acc[6]);
            acc[7]  = ffma2(aA.x, w7, acc[7]);
            acc[8]  = ffma2(aA.y, w0, acc[8]);
            acc[9]  = ffma2(aA.y, w1, acc[9]);
            acc[10] = ffma2(aA.y, w2, acc[10]);
            acc[11] = ffma2(aA.y, w3, acc[11]);
            acc[12] = ffma2(aA.y, w4, acc[12]);
            acc[13] = ffma2(aA.y, w5, acc[13]);
            acc[14] = ffma2(aA.y, w6, acc[14]);
            acc[15] = ffma2(aA.y, w7, acc[15]);
            acc[16] = ffma2(aB.x, w0, acc[16]);
            acc[17] = ffma2(aB.x, w1, acc[17]);
            acc[18] = ffma2(aB.x, w2, acc[18]);
            acc[19] = ffma2(aB.x, w3, acc[19]);
            acc[20] = ffma2(aB.x, w4, acc[20]);
            acc[21] = ffma2(aB.x, w5, acc[21]);
            acc[22] = ffma2(aB.x, w6, acc[22]);
            acc[23] = ffma2(aB.x, w7, acc[23]);
            acc[24] = ffma2(aB.y, w0, acc[24]);
            acc[25] = ffma2(aB.y, w1, acc[25]);
            acc[26] = ffma2(aB.y, w2, acc[26]);
            acc[27] = ffma2(aB.y, w3, acc[27]);
            acc[28] = ffma2(aB.y, w4, acc[28]);
            acc[29] = ffma2(aB.y, w5, acc[29]);
            acc[30] = ffma2(aB.y, w6, acc[30]);
            acc[31] = ffma2(aB.y, w7, acc[31]);
        }
        __syncthreads();
    }

    // epilogue: rows 8ty..8ty+7 = batch group g = ty, r = 0..7.
    // For each owned col j: store all 8 r-values contiguously (C[...][j][r]).
    float4 bias0 = *(const float4*)&g_c0[jb + 4 * tx];
    float4 bias1 = *(const float4*)&g_c0[jb + 128 + 4 * tx];
    float bias[8] = {bias0.x, bias0.y, bias0.z, bias0.w,
                     bias1.x, bias1.y, bias1.z, bias1.w};
#pragma unroll
    for (int c = 0; c < 8; c++) {
        int j = jb + ((c < 4) ? (4 * tx + c) : (128 + 4 * tx + c - 4));
        float bv = bias[c];
        float2 u0 = unpack2(acc[0 * 8 + c]);   // r = 0,1
        float2 u1 = unpack2(acc[1 * 8 + c]);   // r = 2,3
        float2 u2 = unpack2(acc[2 * 8 + c]);   // r = 4,5
        float2 u3 = unpack2(acc[3 * 8 + c]);   // r = 6,7
        float4 lo = make_float4(u0.x + bv, u0.y + bv, u1.x + bv, u1.y + bv);
        float4 hi = make_float4(u2.x + bv, u2.y + bv, u3.x + bv, u3.y + bv);
        float* dst = &g_C[(((size_t)s * 8 + ty) * 512 + j) * 8];
        *(float4*)dst = lo;
        *(float4*)(dst + 4) = hi;
    }
}

// ---------------------------------------------------------------------------
// Persistent recurrent kernel: 128 CTAs = 8 groups x 16 col-blocks.
// Single fused GEMM per step: hn = h + (tanh(h@M + C_t) - h)/tau
// R6 skeleton; weights now live in registers as 16 x float4 (unsplatted).
// ---------------------------------------------------------------------------
#define SCR_F 8320           // max(HT = 4352 f, RED = 32*130 ull = 8320 f)
#define RED_STRIDE 130       // ull stride per k-slice row

__global__ void __launch_bounds__(256, 1) rec_kernel(const float* __restrict__ tau,
                                                     float* __restrict__ out) {
    __shared__ __align__(16) float SCR[SCR_F];   // HT (staged h) / RED (partials)

    const int tid = threadIdx.x;
    const int g   = blockIdx.x >> 4;    // batch group
    const int cb  = blockIdx.x & 15;    // column block
    const int j0  = cb * 32;
    const int cg  = tid & 7;            // column sub-group (4 cols)
    const int ks  = tid >> 3;           // k-slice 0..31 (16 k each)
    const int c0  = 4 * cg;

    // --- weights into registers: 16 x float4, held for all 1024 steps ---
    float4 wf[16];
    {
        const float* ws = &g_P[(size_t)(256 + 16 * ks) * 512 + j0 + c0];
#pragma unroll
        for (int i = 0; i < 16; i++)
            wf[i] = __ldg((const float4*)(ws + (size_t)i * 512));
    }

    // --- hoisted epilogue state (output-owning threads: tid < 128) ---
    float ertau = 0.0f;
    ull h_reg = 0ull;
    const float* cpp = g_C;
    float *ghp = g_H, *o0 = out, *o1 = out;
    if (tid < 128) {
        int erp = tid >> 5;             // row pair (rows 2erp, 2erp+1)
        int ec = tid & 31;
        int ej = j0 + ec;
        ertau = 1.0f / __ldg(&tau[ej]);
        cpp = g_C + ((size_t)g * 512 + ej) * 8 + 2 * erp;
        ghp = g_H + (size_t)g * 4096 + ej * 8 + 2 * erp;
        int b0 = g * 8 + 2 * erp;
        o0 = out + ((size_t)b0 * SEQ) * HID + ej;
        o1 = out + ((size_t)(b0 + 1) * SEQ) * HID + ej;
    }

    const float* gHbase = g_H + (size_t)g * 4096;
    unsigned* ctr = &g_ctr[g * 32];
    unsigned bt = 0;
    ull* RED = (ull*)SCR;
    const float* ht_p = SCR + ks * 136;

    for (int t = 0; t < SEQ; t++) {
        // load this step's C early (DRAM latency hidden under stage+kloop)
        ull cv = 0ull;
        if (tid < 128) cv = ldcg8(cpp);

        // stage h into skewed transposed layout HT[(k>>4)*136 + (k&15)*8 + r]
#pragma unroll
        for (int i = 0; i < 4; i++) {
            int v = tid + 256 * i;      // float4-slot over [j][r] = 4096 floats
            float4 d = ldcg4(gHbase + 4 * v);
            int k = v >> 1, half = v & 1;
            *(float4*)&SCR[(k >> 4) * 136 + (k & 15) * 8 + 4 * half] = d;
        }
        __syncthreads();
        {
            ull acc[16];
#pragma unroll
            for (int i = 0; i < 16; i++) acc[i] = 0ull;
#pragma unroll
            for (int i = 0; i < 16; i++) {
                ulonglong2 hA = *(const ulonglong2*)(ht_p + 8 * i);
                ulonglong2 hB = *(const ulonglong2*)(ht_p + 8 * i + 4);
                float4 w = wf[i];
                ull w0 = pack2(w.x, w.x), w1 = pack2(w.y, w.y);
                ull w2 = pack2(w.z, w.z), w3 = pack2(w.w, w.w);
                acc[0]  = ffma2(hA.x, w0, acc[0]);
                acc[1]  = ffma2(hA.x, w1, acc[1]);
                acc[2]  = ffma2(hA.x, w2, acc[2]);
                acc[3]  = ffma2(hA.x, w3, acc[3]);
                acc[4]  = ffma2(hA.y, w0, acc[4]);
                acc[5]  = ffma2(hA.y, w1, acc[5]);
                acc[6]  = ffma2(hA.y, w2, acc[6]);
                acc[7]  = ffma2(hA.y, w3, acc[7]);
                acc[8]  = ffma2(hB.x, w0, acc[8]);
                acc[9]  = ffma2(hB.x, w1, acc[9]);
                acc[10] = ffma2(hB.x, w2, acc[10]);
                acc[11] = ffma2(hB.x, w3, acc[11]);
                acc[12] = ffma2(hB.y, w0, acc[12]);
                acc[13] = ffma2(hB.y, w1, acc[13]);
                acc[14] = ffma2(hB.y, w2, acc[14]);
                acc[15] = ffma2(hB.y, w3, acc[15]);
            }
            __syncthreads();            // done reading HT before RED overwrite
#pragma unroll
            for (int rp = 0; rp < 4; rp++) {
                ulonglong2 v0, v1;
                v0.x = acc[rp * 4 + 0]; v0.y = acc[rp * 4 + 1];
                v1.x = acc[rp * 4 + 2]; v1.y = acc[rp * 4 + 3];
                *(ulonglong2*)&RED[ks * RED_STRIDE + rp * 32 + c0]     = v0;
                *(ulonglong2*)&RED[ks * RED_STRIDE + rp * 32 + c0 + 2] = v1;
            }
        }
        __syncthreads();
        if (tid < 128) {
            const ull* rb = RED + tid;      // partial i at rb[i*RED_STRIDE]
            ull s0 = rb[0];
            ull s1 = rb[RED_STRIDE];
            ull s2 = rb[2 * RED_STRIDE];
            ull s3 = rb[3 * RED_STRIDE];
#pragma unroll
            for (int i = 4; i < 32; i += 4) {
                s0 = add2(s0, rb[(i + 0) * RED_STRIDE]);
                s1 = add2(s1, rb[(i + 1) * RED_STRIDE]);
                s2 = add2(s2, rb[(i + 2) * RED_STRIDE]);
                s3 = add2(s3, rb[(i + 3) * RED_STRIDE]);
            }
            float2 z = unpack2(add2(add2(s0, s1), add2(s2, s3)));
            float2 c = unpack2(cv);
            float d0 = tanhf(z.x + c.x);
            float d1 = tanhf(z.y + c.y);
            float2 h = unpack2(h_reg);
            float hn0 = h.x + (d0 - h.x) * ertau;
            float hn1 = h.y + (d1 - h.y) * ertau;
            h_reg = pack2(hn0, hn1);
            stcg8(ghp, h_reg);
            o0[(size_t)t * HID] = hn0;
            o1[(size_t)t * HID] = hn1;
            cpp += 8 * 4096;            // next t
            __threadfence();            // writers only: release h before arrival
        }
        __syncthreads();
        bt += 16;
        if (tid == 0) {
            asm volatile("red.release.gpu.global.add.u32 [%0], %1;" :: "l"(ctr), "r"(1u) : "memory");
            unsigned v;
            do {
                asm volatile("ld.acquire.gpu.global.u32 %0, [%1];" : "=r"(v) : "l"(ctr) : "memory");
            } while (v < bt);
        }
        __syncthreads();
    }
}

// ---------------------------------------------------------------------------
extern "C" void kernel_launch(void* const* d_in, const int* in_sizes, int n_in,
                              void* d_out, int out_size) {
    (void)in_sizes; (void)n_in; (void)out_size;
    const float* X   = (const float*)d_in[0];
    const float* Wb  = (const float*)d_in[1];
    const float* bb  = (const float*)d_in[2];
    const float* Wh  = (const float*)d_in[3];
    const float* bh  = (const float*)d_in[4];
    const float* tau = (const float*)d_in[5];
    float* out = (float*)d_out;

    init_kernel<<<1, 256>>>();
    c0_kernel<<<1, 512>>>(bb, Wh, bh);
    dim3 pgrid(8, 12);
    pmat_kernel<<<pgrid, 256>>>(Wb, Wh);
    dim3 cgrid(2, SEQ);
    pre_kernel<<<cgrid, 256>>>(X);
    rec_kernel<<<128, 256>>>(tau, out);
}